// round 15
// baseline (speedup 1.0000x reference)
#include <cuda_runtime.h>
#include <cuda_fp16.h>
#include <cstdint>

#define NPTS   65536
#define DIMS   384
#define NK     64
#define ITERS  10
#define NCH    12            // 12 chunks x 32 dims (= 2 ksteps of 16)
#define ACC_CTAS 256
#define ACC_PTS  256

typedef unsigned long long u64;

// ---------------- scratch -----------------------------------------------------
__device__ float g_centers[NK * DIMS];
// B fragments in fp16, exact mma.m16n8k16 order: [kstep s(24)][j(8)][lane(32)][word(2)]
__device__ __align__(16) unsigned short g_cfh16[24 * 8 * 32 * 2 * 2];
__device__ __align__(16) unsigned short g_cfl16[24 * 8 * 32 * 2 * 2];
// A fragments (x split hi/lo), per (CTA block pb, chunk c): 4096 halfs in the
// exact smem layout assign consumes: word off = ((s*8+w)*16+r)*8 + (kk>>1)
__device__ __align__(16) unsigned short g_xfh[(size_t)512 * NCH * 4096];
__device__ __align__(16) unsigned short g_xfl[(size_t)512 * NCH * 4096];
__device__ float g_ccp[NK * 6];          // ||c_k||^2 in 6 fixed-order partials
__device__ int   g_labels[NPTS];
__device__ float g_partials[(size_t)ACC_CTAS * NK * DIMS];
__device__ float g_pcounts[NK * ACC_CTAS];
__device__ float g_proj[NK * DIMS];

// ---------------- helpers ------------------------------------------------------
__device__ __forceinline__ uint32_t h2_as_u32(__half2 h) {
    union { __half2 h; uint32_t u; } cvt;
    cvt.h = h;
    return cvt.u;
}
__device__ __forceinline__ void cp16(const void* smem, const void* gmem) {
    unsigned sa = (unsigned)__cvta_generic_to_shared(smem);
    asm volatile("cp.async.cg.shared.global [%0], [%1], 16;" :: "r"(sa), "l"(gmem));
}
__device__ __forceinline__ void cp_commit() { asm volatile("cp.async.commit_group;"); }
template <int N>
__device__ __forceinline__ void cp_wait() { asm volatile("cp.async.wait_group %0;" :: "n"(N)); }

__device__ __forceinline__ void mma16(float* d, const uint32_t* a, uint32_t b0, uint32_t b1) {
    asm("mma.sync.aligned.m16n8k16.row.col.f32.f16.f16.f32 "
        "{%0,%1,%2,%3},{%4,%5,%6,%7},{%8,%9},{%0,%1,%2,%3};"
        : "+f"(d[0]), "+f"(d[1]), "+f"(d[2]), "+f"(d[3])
        : "r"(a[0]), "r"(a[1]), "r"(a[2]), "r"(a[3]), "r"(b0), "r"(b1));
}

// B-fragment position for (cluster k, dim d), m16n8k16
__device__ __forceinline__ void store_center_frag(int k, int d, float v) {
    const int s = d >> 4, kk = d & 15, j = k >> 3;
    const int t = (kk >> 1) & 3;
    const int lane = (k & 7) * 4 + t;
    const int word = kk >> 3, pos = kk & 1;
    const int off = ((((s * 8 + j) * 32 + lane) * 2) + word) * 2 + pos;
    const __half h = __float2half_rn(v);
    const float lof = v - __half2float(h);
    g_cfh16[off] = __half_as_ushort(h);
    g_cfl16[off] = __half_as_ushort(__float2half_rn(lof));
}

// ---------------- one-time x split into A fragments ----------------------------
// 512 CTAs x 256 threads; identical index math to the old in-assign producer.
__global__ void __launch_bounds__(256) xsplit_kernel(const float* __restrict__ x) {
    const int tid = threadIdx.x;
    const unsigned pcta = blockIdx.x * 128u;
    const int ptb = tid >> 3;
    const int fq  = tid & 7;
    const int sl_ = fq >> 2;
    const int hw  = (fq & 3) * 2;

    for (int c = 0; c < NCH; ++c) {
        const size_t blk = ((size_t)blockIdx.x * NCH + c) * 4096;   // halfs
#pragma unroll
        for (int q = 0; q < 4; ++q) {
            const int pt = ptb + 32 * q;
            const float4 v = *reinterpret_cast<const float4*>(
                &x[(size_t)(pcta + pt) * DIMS + c * 32 + fq * 4]);
            const int w = pt >> 4, r = pt & 15;
            const int off = (((sl_ * 8 + w) * 16 + r) * 8 + hw) * 2;  // halfs
            const __half2 ha = __floats2half2_rn(v.x, v.y);
            const __half2 hb = __floats2half2_rn(v.z, v.w);
            const float2 fa = __half22float2(ha);
            const float2 fb = __half22float2(hb);
            const __half2 la = __floats2half2_rn(v.x - fa.x, v.y - fa.y);
            const __half2 lb = __floats2half2_rn(v.z - fb.x, v.w - fb.y);
            *reinterpret_cast<uint2*>(&g_xfh[blk + off]) =
                make_uint2(h2_as_u32(ha), h2_as_u32(hb));
            *reinterpret_cast<uint2*>(&g_xfl[blk + off]) =
                make_uint2(h2_as_u32(la), h2_as_u32(lb));
        }
    }
}

// ---------------- init centers = first 64 points ------------------------------
__global__ void init_centers_kernel(const float* __restrict__ x) {
    __shared__ float red[DIMS];
    int k = blockIdx.x, d = threadIdx.x;
    float v = x[k * DIMS + d];
    g_centers[k * DIMS + d] = v;
    store_center_frag(k, d, v);
    red[d] = v * v;
    __syncthreads();
    if (d < 6) {
        float s = 0.f;
        for (int i = 0; i < 64; ++i) s += red[d * 64 + i];
        g_ccp[k * 6 + d] = s;
    }
}

// ---------------- assignment: pure cp.async -> LDS -> mma pipeline -------------
// 512 CTAs x 256 threads (8 warps). CTA = 128 points x 64 clusters.
// 3 stages; stage stride SS = 6144 words (24 KB):
//   A_hi [0,2048)  A_lo [2048,4096)  B_hi [4096,5120)  B_lo [5120,6144)
#define SS 6144
extern __shared__ uint32_t asg_sm[];

__device__ __forceinline__ void asg_issue(uint32_t* st, int c, int tid, unsigned blkid) {
    const char* ah = (const char*)&g_xfh[((size_t)blkid * NCH + c) * 4096];
    const char* al = (const char*)&g_xfl[((size_t)blkid * NCH + c) * 4096];
#pragma unroll
    for (int j = 0; j < 2; ++j) {
        const int o = (j * 256 + tid) * 16;
        cp16((char*)(st) + o, ah + o);
        cp16((char*)(st + 2048) + o, al + o);
    }
    cp16((char*)(st + 4096) + tid * 16, (const char*)g_cfh16 + c * 4096 + tid * 16);
    cp16((char*)(st + 5120) + tid * 16, (const char*)g_cfl16 + c * 4096 + tid * 16);
    cp_commit();
}

__global__ void __launch_bounds__(256, 3) assign_kernel() {
    __shared__ float scc[NK];
    const int tid = threadIdx.x;
    const int wid = tid >> 5, lane = tid & 31;
    const unsigned pcta = blockIdx.x * 128u;

    if (tid < NK) {
        const float* p = g_ccp + tid * 6;
        scc[tid] = ((p[0] + p[1]) + (p[2] + p[3])) + (p[4] + p[5]);
    }

#pragma unroll
    for (int st = 0; st < 3; ++st)
        asg_issue(asg_sm + st * SS, st, tid, blockIdx.x);

    float D[8][4];
#pragma unroll
    for (int j = 0; j < 8; ++j)
#pragma unroll
        for (int t = 0; t < 4; ++t) D[j][t] = 0.f;

    const int g = lane >> 2, t = lane & 3;

    for (int c = 0; c < NCH; ++c) {
        uint32_t* S = asg_sm + (c % 3) * SS;
        const uint32_t* SAH = S;
        const uint32_t* SAL = S + 2048;
        const uint32_t* SBH = S + 4096;
        const uint32_t* SBL = S + 5120;

        if (c <= 9) cp_wait<2>();
        else if (c == 10) cp_wait<1>();
        else cp_wait<0>();
        __syncthreads();

#pragma unroll
        for (int s = 0; s < 2; ++s) {
            const int ab = (s * 8 + wid) * 128;   // 16 rows * 8 words
            uint32_t a[4], al[4];
            a[0]  = SAH[ab + g * 8 + t];
            a[1]  = SAH[ab + (g + 8) * 8 + t];
            a[2]  = SAH[ab + g * 8 + t + 4];
            a[3]  = SAH[ab + (g + 8) * 8 + t + 4];
            al[0] = SAL[ab + g * 8 + t];
            al[1] = SAL[ab + (g + 8) * 8 + t];
            al[2] = SAL[ab + g * 8 + t + 4];
            al[3] = SAL[ab + (g + 8) * 8 + t + 4];
#pragma unroll
            for (int j = 0; j < 8; ++j) {
                const uint2 bh = *reinterpret_cast<const uint2*>(&SBH[((s * 8 + j) * 32 + lane) * 2]);
                const uint2 bl = *reinterpret_cast<const uint2*>(&SBL[((s * 8 + j) * 32 + lane) * 2]);
                mma16(D[j], a, bh.x, bh.y);
                mma16(D[j], a, bl.x, bl.y);
                mma16(D[j], al, bh.x, bh.y);
            }
        }
        __syncthreads();

        if (c + 3 < NCH)
            asg_issue(S, c + 3, tid, blockIdx.x);
    }

    // epilogue: dist = cc[n] - 2*dot ; argmin, first-min tiebreak
    float best0 = __int_as_float(0x7f800000), best1 = best0;
    int bi0 = NK, bi1 = NK;
#pragma unroll
    for (int j = 0; j < 8; ++j) {
#pragma unroll
        for (int u = 0; u < 2; ++u) {
            const int n = j * 8 + (lane & 3) * 2 + u;
            const float cc = scc[n];
            const float s0 = fmaf(-2.0f, D[j][u], cc);
            const float s1 = fmaf(-2.0f, D[j][2 + u], cc);
            if (s0 < best0 || (s0 == best0 && n < bi0)) { best0 = s0; bi0 = n; }
            if (s1 < best1 || (s1 == best1 && n < bi1)) { best1 = s1; bi1 = n; }
        }
    }
#pragma unroll
    for (int off = 1; off < 4; off <<= 1) {
        float ob = __shfl_xor_sync(0xffffffffu, best0, off);
        int   oi = __shfl_xor_sync(0xffffffffu, bi0, off);
        if (ob < best0 || (ob == best0 && oi < bi0)) { best0 = ob; bi0 = oi; }
        ob = __shfl_xor_sync(0xffffffffu, best1, off);
        oi = __shfl_xor_sync(0xffffffffu, bi1, off);
        if (ob < best1 || (ob == best1 && oi < bi1)) { best1 = ob; bi1 = oi; }
    }
    if ((lane & 3) == 0) {
        const int r = lane >> 2;
        const unsigned p0 = pcta + wid * 16;
        g_labels[p0 + r] = bi0;
        g_labels[p0 + r + 8] = bi1;
    }
}

// ---------------- segment-sum accumulation (R12 proven version) ------------------
extern __shared__ float acc_smem[];
__global__ void __launch_bounds__(384, 2) accum_kernel(const float* __restrict__ x) {
    __shared__ int s_lb[ACC_PTS];
    const int t = threadIdx.x;

    for (int i = t; i < NK * DIMS; i += 384) acc_smem[i] = 0.f;
    const int pbase = blockIdx.x * ACC_PTS;
    if (t < ACC_PTS) s_lb[t] = g_labels[pbase + t];
    __syncthreads();

    const float* xp = x + (size_t)pbase * DIMS + t;
    float cnt = 0.f;

    for (int j = 0; j < ACC_PTS; j += 32) {
        float v[32];
#pragma unroll
        for (int i = 0; i < 32; ++i)
            v[i] = __ldg(xp + (unsigned)(j + i) * DIMS);
        int lb[32];
#pragma unroll
        for (int i = 0; i < 32; ++i)
            lb[i] = s_lb[j + i];
#pragma unroll
        for (int i = 0; i < 32; ++i) {
            acc_smem[lb[i] * DIMS + t] += v[i];
            cnt += (lb[i] == t) ? 1.f : 0.f;
        }
    }
    __syncthreads();

    float* outp = g_partials + (size_t)blockIdx.x * (NK * DIMS);
    for (int i = t; i < NK * DIMS; i += 384) outp[i] = acc_smem[i];
    if (t < NK) g_pcounts[t * ACC_CTAS + blockIdx.x] = cnt;
}

// ---------------- partials reduction -> new centers + ||c||^2 partials -----------
__global__ void __launch_bounds__(256, 4) reduce_kernel() {
    __shared__ float sp[256];
    __shared__ float sv[4][64];
    __shared__ float sq[64];
    const int b = blockIdx.x;
    const int k = b / 6, dp = b % 6;
    const int t = threadIdx.x;
    const int g = t >> 6, e = t & 63;
    const int d = dp * 64 + e;

    sp[t] = g_pcounts[k * ACC_CTAS + t];

    const float* pp = g_partials + (size_t)(g * 64) * (NK * DIMS) + k * DIMS + d;
    float s = 0.f;
    for (int c = 0; c < 64; c += 16) {
#pragma unroll
        for (int i = 0; i < 16; ++i)
            s += __ldg(pp + (size_t)(c + i) * (NK * DIMS));
    }
    sv[g][e] = s;
    __syncthreads();

    for (int st = 128; st > 0; st >>= 1) {
        if (t < st) sp[t] += sp[t + st];
        __syncthreads();
    }
    const float cnt = sp[0];

    if (t < 64) {
        const float sum = ((sv[0][t] + sv[1][t]) + sv[2][t]) + sv[3][t];
        const int dd = dp * 64 + t;
        const int ee = k * DIMS + dd;
        const float v = (cnt > 0.f) ? (sum / fmaxf(cnt, 1.f)) : g_centers[ee];
        g_centers[ee] = v;
        store_center_frag(k, dd, v);
        sq[t] = v * v;
    }
    __syncthreads();
    for (int st = 32; st > 0; st >>= 1) {
        if (t < st) sq[t] += sq[t + st];
        __syncthreads();
    }
    if (t == 0) g_ccp[k * 6 + dp] = sq[0];
}

// ---------------- proj = centers @ W^T + b ----------------------------------------
__global__ void proj_kernel(const float* __restrict__ W, const float* __restrict__ b) {
    __shared__ float cs[DIMS];
    const int k = blockIdx.x, d = threadIdx.x;
    cs[d] = g_centers[k * DIMS + d];
    __syncthreads();
    const float4* Wr = reinterpret_cast<const float4*>(W + (size_t)d * DIMS);
    float acc = 0.f;
#pragma unroll 4
    for (int i = 0; i < DIMS / 4; ++i) {
        const float4 w = Wr[i];
        acc += cs[4 * i] * w.x + cs[4 * i + 1] * w.y
             + cs[4 * i + 2] * w.z + cs[4 * i + 3] * w.w;
    }
    g_proj[k * DIMS + d] = acc + b[d];
}

// ---------------- scatter out[p] = proj[label[p]] ---------------------------------
__global__ void scatter_kernel(float* __restrict__ out) {
    const unsigned idx = blockIdx.x * 256u + threadIdx.x;
    const int p = idx / (DIMS / 4), r = idx % (DIMS / 4);
    const int lb = g_labels[p];
    reinterpret_cast<float4*>(out)[idx] =
        reinterpret_cast<const float4*>(g_proj)[lb * (DIMS / 4) + r];
}

// ---------------- launch ------------------------------------------------------------
extern "C" void kernel_launch(void* const* d_in, const int* in_sizes, int n_in,
                              void* d_out, int out_size) {
    const float* x = (const float*)d_in[0];
    const float* W = (const float*)d_in[1];
    const float* b = (const float*)d_in[2];
    float* out = (float*)d_out;

    const int asg_smem_bytes = 3 * SS * 4;                       // 73728
    const int acc_smem_bytes = NK * DIMS * (int)sizeof(float);   // 98304

    cudaFuncSetAttribute(assign_kernel, cudaFuncAttributeMaxDynamicSharedMemorySize,
                         asg_smem_bytes);
    cudaFuncSetAttribute(accum_kernel, cudaFuncAttributeMaxDynamicSharedMemorySize,
                         acc_smem_bytes);

    xsplit_kernel<<<512, 256>>>(x);
    init_centers_kernel<<<NK, DIMS>>>(x);

    for (int it = 0; it < ITERS; ++it) {
        assign_kernel<<<NPTS / 128, 256, asg_smem_bytes>>>();
        accum_kernel<<<ACC_CTAS, 384, acc_smem_bytes>>>(x);
        reduce_kernel<<<6 * NK, 256>>>();
    }
    assign_kernel<<<NPTS / 128, 256, asg_smem_bytes>>>();

    proj_kernel<<<NK, DIMS>>>(W, b);
    scatter_kernel<<<(NPTS * (DIMS / 4)) / 256, 256>>>(out);
}

// round 16
// speedup vs baseline: 1.0241x; 1.0241x over previous
#include <cuda_runtime.h>
#include <cuda_fp16.h>
#include <cstdint>

#define NPTS   65536
#define DIMS   384
#define NK     64
#define ITERS  10
#define NCH    12            // 12 chunks x 32 dims (= 2 ksteps of 16)
#define ACC_CTAS 128
#define ACC_PTS  512

typedef unsigned long long u64;

// ---------------- scratch -----------------------------------------------------
__device__ float g_centers[NK * DIMS];
// B fragments in fp16, exact mma.m16n8k16 order: [kstep s(24)][j(8)][lane(32)][word(2)]
__device__ __align__(16) unsigned short g_cfh16[24 * 8 * 32 * 2 * 2];
__device__ __align__(16) unsigned short g_cfl16[24 * 8 * 32 * 2 * 2];
__device__ float g_ccp[NK * 6];          // ||c_k||^2 in 6 fixed-order partials
__device__ int   g_labels[NPTS];
__device__ float g_partials[(size_t)ACC_CTAS * NK * DIMS];   // 12.6 MB
__device__ float g_pcounts[NK * ACC_CTAS];
__device__ float g_proj[NK * DIMS];

// ---------------- helpers ------------------------------------------------------
__device__ __forceinline__ uint32_t h2_as_u32(__half2 h) {
    union { __half2 h; uint32_t u; } cvt;
    cvt.h = h;
    return cvt.u;
}
__device__ __forceinline__ void cp16(const void* smem, const void* gmem) {
    unsigned sa = (unsigned)__cvta_generic_to_shared(smem);
    asm volatile("cp.async.cg.shared.global [%0], [%1], 16;" :: "r"(sa), "l"(gmem));
}
__device__ __forceinline__ void cp_commit() { asm volatile("cp.async.commit_group;"); }
template <int N>
__device__ __forceinline__ void cp_wait() { asm volatile("cp.async.wait_group %0;" :: "n"(N)); }

__device__ __forceinline__ void mma16(float* d, const uint32_t* a, uint32_t b0, uint32_t b1) {
    asm("mma.sync.aligned.m16n8k16.row.col.f32.f16.f16.f32 "
        "{%0,%1,%2,%3},{%4,%5,%6,%7},{%8,%9},{%0,%1,%2,%3};"
        : "+f"(d[0]), "+f"(d[1]), "+f"(d[2]), "+f"(d[3])
        : "r"(a[0]), "r"(a[1]), "r"(a[2]), "r"(a[3]), "r"(b0), "r"(b1));
}

// B-fragment position for (cluster k, dim d), m16n8k16
__device__ __forceinline__ void store_center_frag(int k, int d, float v) {
    const int s = d >> 4, kk = d & 15, j = k >> 3;
    const int t = (kk >> 1) & 3;
    const int lane = (k & 7) * 4 + t;
    const int word = kk >> 3, pos = kk & 1;
    const int off = ((((s * 8 + j) * 32 + lane) * 2) + word) * 2 + pos;
    const __half h = __float2half_rn(v);
    const float lof = v - __half2float(h);
    g_cfh16[off] = __half_as_ushort(h);
    g_cfl16[off] = __half_as_ushort(__float2half_rn(lof));
}

// ---------------- init centers = first 64 points ------------------------------
__global__ void init_centers_kernel(const float* __restrict__ x) {
    __shared__ float red[DIMS];
    int k = blockIdx.x, d = threadIdx.x;
    float v = x[k * DIMS + d];
    g_centers[k * DIMS + d] = v;
    store_center_frag(k, d, v);
    red[d] = v * v;
    __syncthreads();
    if (d < 6) {
        float s = 0.f;
        for (int i = 0; i < 64; ++i) s += red[d * 64 + i];
        g_ccp[k * 6 + d] = s;
    }
}

// ---------------- assignment via mma.sync 3xFP16 (R14 proven version) ----------
extern __shared__ uint32_t asg_sm[];

__global__ void __launch_bounds__(256, 2) assign_kernel(const float* __restrict__ x) {
    __shared__ float scc[NK];
    const int tid = threadIdx.x;
    const int wid = tid >> 5, lane = tid & 31;
    const unsigned pcta = blockIdx.x * 128u;

    if (tid < NK) {
        const float* p = g_ccp + tid * 6;
        scc[tid] = ((p[0] + p[1]) + (p[2] + p[3])) + (p[4] + p[5]);
    }

#pragma unroll
    for (int c0 = 0; c0 < 2; ++c0) {
        uint32_t* bh = asg_sm + c0 * 8192 + 6144;
        uint32_t* bl = asg_sm + c0 * 8192 + 7168;
        const char* sh = (const char*)g_cfh16 + c0 * 4096;
        const char* sl = (const char*)g_cfl16 + c0 * 4096;
        cp16((char*)bh + tid * 16, sh + tid * 16);
        cp16((char*)bl + tid * 16, sl + tid * 16);
        cp_commit();
    }

    const int ptb = tid >> 3;
    const int fq  = tid & 7;
    float4 rx[4], rn[4];
#pragma unroll
    for (int q = 0; q < 4; ++q) {
        const int pt = ptb + 32 * q;
        rx[q] = *reinterpret_cast<const float4*>(&x[(size_t)(pcta + pt) * DIMS + fq * 4]);
    }

    float D[8][4];
#pragma unroll
    for (int j = 0; j < 8; ++j)
#pragma unroll
        for (int t = 0; t < 4; ++t) D[j][t] = 0.f;

    const int sl_ = fq >> 2;
    const int hw  = (fq & 3) * 2;

    for (int c = 0; c < NCH; ++c) {
        const int buf = c & 1;
        uint32_t* SAH = asg_sm + buf * 8192;
        uint32_t* SAL = SAH + 3072;
        const uint32_t* SBH = SAH + 6144;
        const uint32_t* SBL = SAH + 7168;

        if (c < NCH - 2) cp_wait<1>(); else cp_wait<0>();

#pragma unroll
        for (int q = 0; q < 4; ++q) {
            const int pt = ptb + 32 * q;
            const int w = pt >> 4, r = pt & 15;
            const int off = ((sl_ * 8 + w) * 16 + r) * 12 + hw;
            const __half2 ha = __floats2half2_rn(rx[q].x, rx[q].y);
            const __half2 hb = __floats2half2_rn(rx[q].z, rx[q].w);
            const float2 fa = __half22float2(ha);
            const float2 fb = __half22float2(hb);
            const __half2 la = __floats2half2_rn(rx[q].x - fa.x, rx[q].y - fa.y);
            const __half2 lb = __floats2half2_rn(rx[q].z - fb.x, rx[q].w - fb.y);
            *reinterpret_cast<uint2*>(SAH + off) =
                make_uint2(h2_as_u32(ha), h2_as_u32(hb));
            *reinterpret_cast<uint2*>(SAL + off) =
                make_uint2(h2_as_u32(la), h2_as_u32(lb));
        }

        if (c + 1 < NCH) {
#pragma unroll
            for (int q = 0; q < 4; ++q) {
                const int pt = ptb + 32 * q;
                rn[q] = *reinterpret_cast<const float4*>(
                    &x[(size_t)(pcta + pt) * DIMS + (c + 1) * 32 + fq * 4]);
            }
        }

        __syncthreads();

        const int g = lane >> 2, t = lane & 3;
#pragma unroll
        for (int s = 0; s < 2; ++s) {
            const int ab = (s * 8 + wid) * 192;
            uint32_t a[4], al[4];
            a[0]  = SAH[ab + g * 12 + t];
            a[1]  = SAH[ab + (g + 8) * 12 + t];
            a[2]  = SAH[ab + g * 12 + t + 4];
            a[3]  = SAH[ab + (g + 8) * 12 + t + 4];
            al[0] = SAL[ab + g * 12 + t];
            al[1] = SAL[ab + (g + 8) * 12 + t];
            al[2] = SAL[ab + g * 12 + t + 4];
            al[3] = SAL[ab + (g + 8) * 12 + t + 4];
#pragma unroll
            for (int j = 0; j < 8; ++j) {
                const uint2 bh = *reinterpret_cast<const uint2*>(&SBH[((s * 8 + j) * 32 + lane) * 2]);
                const uint2 bl = *reinterpret_cast<const uint2*>(&SBL[((s * 8 + j) * 32 + lane) * 2]);
                mma16(D[j], a, bh.x, bh.y);
                mma16(D[j], a, bl.x, bl.y);
                mma16(D[j], al, bh.x, bh.y);
            }
        }
        __syncthreads();

        if (c + 2 < NCH) {
            uint32_t* bh = asg_sm + buf * 8192 + 6144;
            uint32_t* bl = asg_sm + buf * 8192 + 7168;
            const char* sh = (const char*)g_cfh16 + (c + 2) * 4096;
            const char* sl = (const char*)g_cfl16 + (c + 2) * 4096;
            cp16((char*)bh + tid * 16, sh + tid * 16);
            cp16((char*)bl + tid * 16, sl + tid * 16);
            cp_commit();
        }
#pragma unroll
        for (int q = 0; q < 4; ++q) rx[q] = rn[q];
    }

    float best0 = __int_as_float(0x7f800000), best1 = best0;
    int bi0 = NK, bi1 = NK;
#pragma unroll
    for (int j = 0; j < 8; ++j) {
#pragma unroll
        for (int u = 0; u < 2; ++u) {
            const int n = j * 8 + (lane & 3) * 2 + u;
            const float cc = scc[n];
            const float s0 = fmaf(-2.0f, D[j][u], cc);
            const float s1 = fmaf(-2.0f, D[j][2 + u], cc);
            if (s0 < best0 || (s0 == best0 && n < bi0)) { best0 = s0; bi0 = n; }
            if (s1 < best1 || (s1 == best1 && n < bi1)) { best1 = s1; bi1 = n; }
        }
    }
#pragma unroll
    for (int off = 1; off < 4; off <<= 1) {
        float ob = __shfl_xor_sync(0xffffffffu, best0, off);
        int   oi = __shfl_xor_sync(0xffffffffu, bi0, off);
        if (ob < best0 || (ob == best0 && oi < bi0)) { best0 = ob; bi0 = oi; }
        ob = __shfl_xor_sync(0xffffffffu, best1, off);
        oi = __shfl_xor_sync(0xffffffffu, bi1, off);
        if (ob < best1 || (ob == best1 && oi < bi1)) { best1 = ob; bi1 = oi; }
    }
    if ((lane & 3) == 0) {
        const int r = lane >> 2;
        const unsigned p0 = pcta + wid * 16;
        g_labels[p0 + r] = bi0;
        g_labels[p0 + r + 8] = bi1;
    }
}

// ---------------- segment-sum accumulation (R3 two-copy shape, 512 pts/CTA) ------
// 128 CTAs x 768 threads; copy c = threads [c*384, c*384+384) owns a full 64x384
// smem accumulator and handles the contiguous half of the CTA's 512 points in
// ascending order. Merge on write (fixed order). Conflict-free, deterministic.
extern __shared__ float acc_smem[];
__global__ void __launch_bounds__(768, 1) accum_kernel(const float* __restrict__ x) {
    __shared__ int   s_lb[ACC_PTS];
    __shared__ float s_cnt[2][NK];
    const int tid  = threadIdx.x;
    const int copy = (tid >= DIMS) ? 1 : 0;
    const int t    = tid - copy * DIMS;
    float* my = acc_smem + copy * (NK * DIMS);

    for (int i = tid; i < 2 * NK * DIMS; i += 768) acc_smem[i] = 0.f;
    const int pbase = blockIdx.x * ACC_PTS;
    if (tid < ACC_PTS) s_lb[tid] = g_labels[pbase + tid];
    __syncthreads();

    const int half = ACC_PTS / 2;   // 256
    const float* xp = x + (size_t)(pbase + copy * half) * DIMS + t;
    const int l0 = copy * half;
    float cnt = 0.f;

    for (int j = 0; j < half; j += 32) {
        float v[32];
#pragma unroll
        for (int i = 0; i < 32; ++i)
            v[i] = __ldg(xp + (unsigned)(j + i) * DIMS);
        int lb[32];
#pragma unroll
        for (int i = 0; i < 32; ++i)
            lb[i] = s_lb[l0 + j + i];
#pragma unroll
        for (int i = 0; i < 32; ++i) {
            my[lb[i] * DIMS + t] += v[i];
            cnt += (lb[i] == t) ? 1.f : 0.f;
        }
    }
    if (t < NK) s_cnt[copy][t] = cnt;
    __syncthreads();

    float* outp = g_partials + (size_t)blockIdx.x * (NK * DIMS);
    for (int i = tid; i < NK * DIMS; i += 768)
        outp[i] = acc_smem[i] + acc_smem[i + NK * DIMS];
    if (tid < NK) g_pcounts[tid * ACC_CTAS + blockIdx.x] = s_cnt[0][tid] + s_cnt[1][tid];
}

// ---------------- partials reduction -> new centers + ||c||^2 partials -----------
// 384 CTAs x 256 threads; 4 groups of 64 threads each sum 32 partials ascending.
__global__ void __launch_bounds__(256, 4) reduce_kernel() {
    __shared__ float sp[256];
    __shared__ float sv[4][64];
    __shared__ float sq[64];
    const int b = blockIdx.x;
    const int k = b / 6, dp = b % 6;
    const int t = threadIdx.x;
    const int g = t >> 6, e = t & 63;
    const int d = dp * 64 + e;

    sp[t] = (t < ACC_CTAS) ? g_pcounts[k * ACC_CTAS + t] : 0.f;

    const float* pp = g_partials + (size_t)(g * 32) * (NK * DIMS) + k * DIMS + d;
    float s = 0.f;
    for (int c = 0; c < 32; c += 16) {
#pragma unroll
        for (int i = 0; i < 16; ++i)
            s += __ldg(pp + (size_t)(c + i) * (NK * DIMS));
    }
    sv[g][e] = s;
    __syncthreads();

    for (int st = 128; st > 0; st >>= 1) {
        if (t < st) sp[t] += sp[t + st];
        __syncthreads();
    }
    const float cnt = sp[0];

    if (t < 64) {
        const float sum = ((sv[0][t] + sv[1][t]) + sv[2][t]) + sv[3][t];
        const int dd = dp * 64 + t;
        const int ee = k * DIMS + dd;
        const float v = (cnt > 0.f) ? (sum / fmaxf(cnt, 1.f)) : g_centers[ee];
        g_centers[ee] = v;
        store_center_frag(k, dd, v);
        sq[t] = v * v;
    }
    __syncthreads();
    for (int st = 32; st > 0; st >>= 1) {
        if (t < st) sq[t] += sq[t + st];
        __syncthreads();
    }
    if (t == 0) g_ccp[k * 6 + dp] = sq[0];
}

// ---------------- proj = centers @ W^T + b ----------------------------------------
__global__ void proj_kernel(const float* __restrict__ W, const float* __restrict__ b) {
    __shared__ float cs[DIMS];
    const int k = blockIdx.x, d = threadIdx.x;
    cs[d] = g_centers[k * DIMS + d];
    __syncthreads();
    const float4* Wr = reinterpret_cast<const float4*>(W + (size_t)d * DIMS);
    float acc = 0.f;
#pragma unroll 4
    for (int i = 0; i < DIMS / 4; ++i) {
        const float4 w = Wr[i];
        acc += cs[4 * i] * w.x + cs[4 * i + 1] * w.y
             + cs[4 * i + 2] * w.z + cs[4 * i + 3] * w.w;
    }
    g_proj[k * DIMS + d] = acc + b[d];
}

// ---------------- scatter out[p] = proj[label[p]] ---------------------------------
__global__ void scatter_kernel(float* __restrict__ out) {
    const unsigned idx = blockIdx.x * 256u + threadIdx.x;
    const int p = idx / (DIMS / 4), r = idx % (DIMS / 4);
    const int lb = g_labels[p];
    reinterpret_cast<float4*>(out)[idx] =
        reinterpret_cast<const float4*>(g_proj)[lb * (DIMS / 4) + r];
}

// ---------------- launch ------------------------------------------------------------
extern "C" void kernel_launch(void* const* d_in, const int* in_sizes, int n_in,
                              void* d_out, int out_size) {
    const float* x = (const float*)d_in[0];
    const float* W = (const float*)d_in[1];
    const float* b = (const float*)d_in[2];
    float* out = (float*)d_out;

    const int asg_smem_bytes = 2 * 8192 * 4;                       // 65536
    const int acc_smem_bytes = 2 * NK * DIMS * (int)sizeof(float); // 196608

    cudaFuncSetAttribute(assign_kernel, cudaFuncAttributeMaxDynamicSharedMemorySize,
                         asg_smem_bytes);
    cudaFuncSetAttribute(accum_kernel, cudaFuncAttributeMaxDynamicSharedMemorySize,
                         acc_smem_bytes);

    init_centers_kernel<<<NK, DIMS>>>(x);

    for (int it = 0; it < ITERS; ++it) {
        assign_kernel<<<NPTS / 128, 256, asg_smem_bytes>>>(x);
        accum_kernel<<<ACC_CTAS, 768, acc_smem_bytes>>>(x);
        reduce_kernel<<<6 * NK, 256>>>();
    }
    assign_kernel<<<NPTS / 128, 256, asg_smem_bytes>>>(x);

    proj_kernel<<<NK, DIMS>>>(W, b);
    scatter_kernel<<<(NPTS * (DIMS / 4)) / 256, 256>>>(out);
}